// round 13
// baseline (speedup 1.0000x reference)
#include <cuda_runtime.h>
#include <cuda_fp16.h>
#include <cstdint>

// Problem constants
#define NN    16384
#define KK    25
#define DD    256
#define OUTD  256
#define NTOT  100000
#define BAG   8
#define KDIM  1024

// g_X / g_M hold fp16 (same 11-bit mantissa as tf32). K-dim pair-permuted
// within each 16-half block: pair p -> slot [p0,p4,p1,p5,p2,p6,p3,p7], so one
// LDS.64 at byte offset t*8 yields one m16n8k16 fragment K-group. Applied to
// BOTH operands -> dot products unchanged.

__device__ __half g_M[OUTD * KDIM];          // fused weights (512 KB)
__device__ __half g_X[(size_t)NN * KDIM];    // gathered features (32 MB)

__device__ __forceinline__ void cp_async16(void* smem, const void* gmem) {
    uint32_t s = (uint32_t)__cvta_generic_to_shared(smem);
    asm volatile("cp.async.cg.shared.global [%0], [%1], 16;" :: "r"(s), "l"(gmem));
}

// ---------------------------------------------------------------------------
// K1: fuse weights.  M_c = W_comp[:, c*256:(c+1)*256] @ (W_rel[c] | W_self)
// 2 o-rows per block -> 512 blocks.  Runs on a side stream, hidden under K2.
// ---------------------------------------------------------------------------
__global__ void __launch_bounds__(256) fuse_weights_kernel(
    const float* __restrict__ W_self,
    const float* __restrict__ W_rel,
    const float* __restrict__ W_comp)
{
    const int c  = blockIdx.x >> 7;
    const int o0 = (blockIdx.x & 127) * 2;

    __shared__ float2 s_w[DD];
    {
        int j = threadIdx.x;
        s_w[j] = make_float2(W_comp[(size_t)o0 * KDIM + c * DD + j],
                             W_comp[(size_t)(o0 + 1) * KDIM + c * DD + j]);
    }
    __syncthreads();

    const float* Wsrc = (c < 3) ? (W_rel + (size_t)c * OUTD * DD) : W_self;
    const int d = threadIdx.x;

    float acc0 = 0.f, acc1 = 0.f;
#pragma unroll 8
    for (int j = 0; j < DD; ++j) {
        float v = __ldg(Wsrc + (size_t)j * DD + d);
        float2 w = s_w[j];
        acc0 += w.x * v;
        acc1 += w.y * v;
    }
    const int h = d & 15, p = h >> 1, i = h & 1;
    const int slot = ((p & 3) << 1) | ((p >> 2) & 1);
    const int pd = (d & ~15) + (slot << 1) + i;
    g_M[(size_t)o0 * KDIM + c * DD + pd]       = __float2half_rn(acc0);
    g_M[(size_t)(o0 + 1) * KDIM + c * DD + pd] = __float2half_rn(acc1);
}

// ---------------------------------------------------------------------------
// K2: gather + mean -> g_X (fp16, pair-permuted K)  [R9 version — at its
// random-access DRAM ceiling (~70%); do not touch]
// Block = 256 threads = 4 nodes x 64 float4 lanes; grid = (N/4, 4)
// ---------------------------------------------------------------------------
__global__ void __launch_bounds__(256) gather_mean_kernel(
    const int*   __restrict__ nodes,
    const int*   __restrict__ neigh_idx,
    const float* __restrict__ table_self,
    const float* __restrict__ tables_to)
{
    const int c   = blockIdx.y;
    const int sub = threadIdx.x >> 6;
    const int d4  = threadIdx.x & 63;
    const int n   = blockIdx.x * 4 + sub;
    const int s0  = ((d4 & 1) << 2) | ((d4 >> 1) & 1);   // [0,4,1,5][d4&3]

    if (c == 3) {
        int i = __ldg(nodes + n);
        float4 v = reinterpret_cast<const float4*>(table_self + (size_t)i * DD)[d4];
        __half* dst = g_X + (size_t)n * KDIM + 3 * DD + ((d4 >> 2) << 4);
        *reinterpret_cast<__half2*>(dst + s0 * 2)       = __floats2half2_rn(v.x, v.y);
        *reinterpret_cast<__half2*>(dst + (s0 + 2) * 2) = __floats2half2_rn(v.z, v.w);
        return;
    }

    __shared__ int s_idx[4][KK];
    if (threadIdx.x < 4 * KK) {
        int nn = blockIdx.x * 4 + threadIdx.x / KK;
        int kk = threadIdx.x % KK;
        s_idx[threadIdx.x / KK][kk] = neigh_idx[((size_t)c * NN + nn) * KK + kk];
    }
    __syncthreads();

    const float* tbl = tables_to + (size_t)c * NTOT * DD;
    float4 acc = make_float4(0.f, 0.f, 0.f, 0.f);
#pragma unroll
    for (int k = 0; k < KK; ++k) {
        int i = s_idx[sub][k];
        float4 v = reinterpret_cast<const float4*>(tbl + (size_t)i * DD)[d4];
        acc.x += v.x; acc.y += v.y; acc.z += v.z; acc.w += v.w;
    }
    const float s = 1.f / (float)KK;
    __half* dst = g_X + (size_t)n * KDIM + (size_t)c * DD + ((d4 >> 2) << 4);
    *reinterpret_cast<__half2*>(dst + s0 * 2)       = __floats2half2_rn(acc.x * s, acc.y * s);
    *reinterpret_cast<__half2*>(dst + (s0 + 2) * 2) = __floats2half2_rn(acc.z * s, acc.w * s);
}

// ---------------------------------------------------------------------------
// K3: H = relu(X @ M^T); out = bag-mean(H, 8)
// FP16 mma m16n8k16.  CTA 128x128, 128 threads (4 warps, 2m x 2n, warp tile
// 64x64 — minimal 2x smem-read redundancy), BK=32 halves (64B rows),
// *** 3-stage cp.async ring, ONE __syncthreads per panel ***,
// 96B smem row stride (conflict-free LDS.64).
// ---------------------------------------------------------------------------
#define GBM 128
#define GBN 128
#define BKH 32
#define SROWH 48
#define STAGE_H (GBM * SROWH)             // halves per matrix per stage
#define STAGE_TOT (2 * STAGE_H)           // A+B per stage (12288 halves, 24 KB)
#define NKC (KDIM / BKH)                  // 32 panels
#define CLD 132
#define G_SMEM_BYTES (3 * STAGE_TOT * 2)  // 73728 B (>= epilogue 67584)

__global__ void __launch_bounds__(128, 2) gemm_relu_bag_kernel(float* __restrict__ out)
{
    extern __shared__ __align__(16) char dynsm[];
    __half* smemh = reinterpret_cast<__half*>(dynsm);

    const int tid  = threadIdx.x;
    const int lane = tid & 31;
    const int wid  = tid >> 5;
    const int wm   = wid & 1;
    const int wn   = wid >> 1;
    const int g    = lane >> 2;
    const int t    = lane & 3;

    const __half* Abase = g_X + (size_t)blockIdx.x * GBM * KDIM;
    const __half* Bbase = g_M + (size_t)blockIdx.y * GBN * KDIM;

    float acc[4][8][4];
#pragma unroll
    for (int i = 0; i < 4; ++i)
#pragma unroll
        for (int j = 0; j < 8; ++j)
#pragma unroll
            for (int r = 0; r < 4; ++r) acc[i][j][r] = 0.f;

#define FILL_STAGE(slot, kc)                                                   \
    {                                                                          \
        __half* sA_ = smemh + (slot) * STAGE_TOT;                              \
        __half* sB_ = sA_ + STAGE_H;                                           \
        const int ko_ = (kc) * BKH;                                            \
        _Pragma("unroll")                                                      \
        for (int i_ = 0; i_ < 4; ++i_) {                                       \
            int f_ = tid + i_ * 128;                                           \
            int r_ = f_ >> 2;                                                  \
            int c_ = f_ & 3;                                                   \
            cp_async16(sA_ + r_ * SROWH + c_ * 8,                              \
                       Abase + (size_t)r_ * KDIM + ko_ + c_ * 8);              \
            cp_async16(sB_ + r_ * SROWH + c_ * 8,                              \
                       Bbase + (size_t)r_ * KDIM + ko_ + c_ * 8);              \
        }                                                                      \
        asm volatile("cp.async.commit_group;");                                \
    }

    FILL_STAGE(0, 0)
    FILL_STAGE(1, 1)

    for (int kc = 0; kc < NKC; ++kc) {
        // stage kc resident after waiting for everything newer than it except
        // the one in-flight fill (stage kc+1)
        if (kc + 1 < NKC) asm volatile("cp.async.wait_group 1;" ::: "memory");
        else              asm volatile("cp.async.wait_group 0;" ::: "memory");
        __syncthreads();   // also: all warps finished compute(kc-1) -> stage
                           // (kc-1)%3 == (kc+2)%3 is reusable
        if (kc + 2 < NKC) FILL_STAGE((kc + 2) % 3, kc + 2)

        const __half* As = smemh + (kc % 3) * STAGE_TOT;
        const __half* Bs = As + STAGE_H;

#pragma unroll
        for (int kk = 0; kk < 2; ++kk) {
            const int coff = kk * 16 + t * 4;
            uint2 alo[4], ahi[4];
#pragma unroll
            for (int mi = 0; mi < 4; ++mi) {
                int r0 = wm * 64 + mi * 16 + g;
                alo[mi] = *reinterpret_cast<const uint2*>(As + r0 * SROWH + coff);
                ahi[mi] = *reinterpret_cast<const uint2*>(As + (r0 + 8) * SROWH + coff);
            }
#pragma unroll
            for (int nj = 0; nj < 8; ++nj) {
                int cn = wn * 64 + nj * 8 + g;
                uint2 b = *reinterpret_cast<const uint2*>(Bs + cn * SROWH + coff);
#pragma unroll
                for (int mi = 0; mi < 4; ++mi) {
                    asm volatile(
                        "mma.sync.aligned.m16n8k16.row.col.f32.f16.f16.f32 "
                        "{%0,%1,%2,%3}, {%4,%5,%6,%7}, {%8,%9}, {%0,%1,%2,%3};"
                        : "+f"(acc[mi][nj][0]), "+f"(acc[mi][nj][1]),
                          "+f"(acc[mi][nj][2]), "+f"(acc[mi][nj][3])
                        : "r"(alo[mi].x), "r"(ahi[mi].x),
                          "r"(alo[mi].y), "r"(ahi[mi].y),
                          "r"(b.x), "r"(b.y));
                }
            }
        }
    }
#undef FILL_STAGE

    // all warps must finish the last panel before Cs overwrites stage smem
    __syncthreads();

    // ---- epilogue: relu -> Cs[128][132] -> bag-mean(8) -> out ----
    float* Cs = reinterpret_cast<float*>(dynsm);
#pragma unroll
    for (int mi = 0; mi < 4; ++mi) {
#pragma unroll
        for (int nj = 0; nj < 8; ++nj) {
            int r0 = wm * 64 + mi * 16 + g;
            int c0 = wn * 64 + nj * 8 + 2 * t;
            Cs[r0 * CLD + c0]           = fmaxf(acc[mi][nj][0], 0.f);
            Cs[r0 * CLD + c0 + 1]       = fmaxf(acc[mi][nj][1], 0.f);
            Cs[(r0 + 8) * CLD + c0]     = fmaxf(acc[mi][nj][2], 0.f);
            Cs[(r0 + 8) * CLD + c0 + 1] = fmaxf(acc[mi][nj][3], 0.f);
        }
    }
    __syncthreads();

    const int col = tid;
#pragma unroll
    for (int gg = 0; gg < GBM / BAG; ++gg) {
        float s = 0.f;
#pragma unroll
        for (int r = 0; r < BAG; ++r) s += Cs[(gg * BAG + r) * CLD + col];
        out[(size_t)(blockIdx.x * (GBM / BAG) + gg) * OUTD + blockIdx.y * GBN + col]
            = s * (1.f / BAG);
    }
}

// ---------------------------------------------------------------------------
namespace {
struct HxSide {
    cudaStream_t side;
    cudaEvent_t  evFork, evJoin;
    HxSide() {
        cudaStreamCreateWithFlags(&side, cudaStreamNonBlocking);
        cudaEventCreateWithFlags(&evFork, cudaEventDisableTiming);
        cudaEventCreateWithFlags(&evJoin, cudaEventDisableTiming);
    }
};
HxSide hx;
}

extern "C" void kernel_launch(void* const* d_in, const int* in_sizes, int n_in,
                              void* d_out, int out_size)
{
    (void)in_sizes; (void)n_in; (void)out_size;
    const int*   nodes      = (const int*)  d_in[0];
    const int*   neigh_idx  = (const int*)  d_in[1];
    const float* table_self = (const float*)d_in[2];
    const float* tables_to  = (const float*)d_in[3];
    const float* W_self     = (const float*)d_in[4];
    const float* W_rel      = (const float*)d_in[5];
    const float* W_comp     = (const float*)d_in[6];
    float*       out        = (float*)d_out;

    cudaFuncSetAttribute(gemm_relu_bag_kernel,
                         cudaFuncAttributeMaxDynamicSharedMemorySize,
                         G_SMEM_BYTES);

    cudaEventRecord(hx.evFork, 0);
    gather_mean_kernel<<<dim3(NN / 4, 4), 256>>>(nodes, neigh_idx, table_self, tables_to);

    cudaStreamWaitEvent(hx.side, hx.evFork, 0);
    fuse_weights_kernel<<<512, 256, 0, hx.side>>>(W_self, W_rel, W_comp);
    cudaEventRecord(hx.evJoin, hx.side);

    cudaStreamWaitEvent(0, hx.evJoin, 0);
    gemm_relu_bag_kernel<<<dim3(NN / GBM, OUTD / GBN), 128, G_SMEM_BYTES>>>(out);
}

// round 14
// speedup vs baseline: 1.0292x; 1.0292x over previous
#include <cuda_runtime.h>
#include <cuda_fp16.h>
#include <cstdint>

// Problem constants
#define NN    16384
#define KK    25
#define DD    256
#define OUTD  256
#define NTOT  100000
#define BAG   8
#define KDIM  1024

// g_X / g_M hold fp16 (same 11-bit mantissa as tf32). K-dim pair-permuted
// within each 16-half block: pair p -> slot [p0,p4,p1,p5,p2,p6,p3,p7], so one
// LDS.64 at byte offset t*8 yields one m16n8k16 fragment K-group. Applied to
// BOTH operands -> dot products unchanged.

__device__ __half g_M[OUTD * KDIM];          // fused weights (512 KB)
__device__ __half g_X[(size_t)NN * KDIM];    // gathered features (32 MB)

__device__ __forceinline__ void cp_async16(void* smem, const void* gmem) {
    uint32_t s = (uint32_t)__cvta_generic_to_shared(smem);
    asm volatile("cp.async.cg.shared.global [%0], [%1], 16;" :: "r"(s), "l"(gmem));
}

// ---------------------------------------------------------------------------
// K1: fuse weights.  M_c = W_comp[:, c*256:(c+1)*256] @ (W_rel[c] | W_self)
// 2 o-rows per block -> 512 blocks.  Runs on a side stream, hidden under K2.
// ---------------------------------------------------------------------------
__global__ void __launch_bounds__(256) fuse_weights_kernel(
    const float* __restrict__ W_self,
    const float* __restrict__ W_rel,
    const float* __restrict__ W_comp)
{
    const int c  = blockIdx.x >> 7;
    const int o0 = (blockIdx.x & 127) * 2;

    __shared__ float2 s_w[DD];
    {
        int j = threadIdx.x;
        s_w[j] = make_float2(W_comp[(size_t)o0 * KDIM + c * DD + j],
                             W_comp[(size_t)(o0 + 1) * KDIM + c * DD + j]);
    }
    __syncthreads();

    const float* Wsrc = (c < 3) ? (W_rel + (size_t)c * OUTD * DD) : W_self;
    const int d = threadIdx.x;

    float acc0 = 0.f, acc1 = 0.f;
#pragma unroll 8
    for (int j = 0; j < DD; ++j) {
        float v = __ldg(Wsrc + (size_t)j * DD + d);
        float2 w = s_w[j];
        acc0 += w.x * v;
        acc1 += w.y * v;
    }
    const int h = d & 15, p = h >> 1, i = h & 1;
    const int slot = ((p & 3) << 1) | ((p >> 2) & 1);
    const int pd = (d & ~15) + (slot << 1) + i;
    g_M[(size_t)o0 * KDIM + c * DD + pd]       = __float2half_rn(acc0);
    g_M[(size_t)(o0 + 1) * KDIM + c * DD + pd] = __float2half_rn(acc1);
}

// ---------------------------------------------------------------------------
// K2: gather + mean -> g_X (fp16, pair-permuted K)  [R9 version — at its
// random-access DRAM ceiling (~70%); do not touch]
// Block = 256 threads = 4 nodes x 64 float4 lanes; grid = (N/4, 4)
// ---------------------------------------------------------------------------
__global__ void __launch_bounds__(256) gather_mean_kernel(
    const int*   __restrict__ nodes,
    const int*   __restrict__ neigh_idx,
    const float* __restrict__ table_self,
    const float* __restrict__ tables_to)
{
    const int c   = blockIdx.y;
    const int sub = threadIdx.x >> 6;
    const int d4  = threadIdx.x & 63;
    const int n   = blockIdx.x * 4 + sub;
    const int s0  = ((d4 & 1) << 2) | ((d4 >> 1) & 1);   // [0,4,1,5][d4&3]

    if (c == 3) {
        int i = __ldg(nodes + n);
        float4 v = reinterpret_cast<const float4*>(table_self + (size_t)i * DD)[d4];
        __half* dst = g_X + (size_t)n * KDIM + 3 * DD + ((d4 >> 2) << 4);
        *reinterpret_cast<__half2*>(dst + s0 * 2)       = __floats2half2_rn(v.x, v.y);
        *reinterpret_cast<__half2*>(dst + (s0 + 2) * 2) = __floats2half2_rn(v.z, v.w);
        return;
    }

    __shared__ int s_idx[4][KK];
    if (threadIdx.x < 4 * KK) {
        int nn = blockIdx.x * 4 + threadIdx.x / KK;
        int kk = threadIdx.x % KK;
        s_idx[threadIdx.x / KK][kk] = neigh_idx[((size_t)c * NN + nn) * KK + kk];
    }
    __syncthreads();

    const float* tbl = tables_to + (size_t)c * NTOT * DD;
    float4 acc = make_float4(0.f, 0.f, 0.f, 0.f);
#pragma unroll
    for (int k = 0; k < KK; ++k) {
        int i = s_idx[sub][k];
        float4 v = reinterpret_cast<const float4*>(tbl + (size_t)i * DD)[d4];
        acc.x += v.x; acc.y += v.y; acc.z += v.z; acc.w += v.w;
    }
    const float s = 1.f / (float)KK;
    __half* dst = g_X + (size_t)n * KDIM + (size_t)c * DD + ((d4 >> 2) << 4);
    *reinterpret_cast<__half2*>(dst + s0 * 2)       = __floats2half2_rn(acc.x * s, acc.y * s);
    *reinterpret_cast<__half2*>(dst + (s0 + 2) * 2) = __floats2half2_rn(acc.z * s, acc.w * s);
}

// ---------------------------------------------------------------------------
// K3: H = relu(X @ M^T); out = bag-mean(H, 8)
// FP16 mma m16n8k16.  CTA 128x128, 128 threads (4 warps, 2m x 2n, warp tile
// 64x64), *** BK=64 halves (16 panels, half the barriers) ***, 2-stage
// cp.async with fill-before-wait (R9 ordering), 160B smem row stride:
// g*160 mod 128 = g*32 -> each 16-lane phase covers disjoint 32B bank
// windows for every kk offset -> conflict-free LDS.64.
// ---------------------------------------------------------------------------
#define GBM 128
#define GBN 128
#define BKH 64                            // halves per panel row (128 B)
#define SROWH 80                          // halves per smem row (160 B)
#define STAGE_H (GBM * SROWH)             // halves per matrix per stage (10240)
#define STAGE_TOT (2 * STAGE_H)           // A+B per stage (40960 B)
#define NKC (KDIM / BKH)                  // 16 panels
#define CLD 132
#define G_SMEM_BYTES (2 * STAGE_TOT * 2)  // 81920 B (>= epilogue 67584)

__global__ void __launch_bounds__(128, 2) gemm_relu_bag_kernel(float* __restrict__ out)
{
    extern __shared__ __align__(16) char dynsm[];
    __half* smemh = reinterpret_cast<__half*>(dynsm);

    const int tid  = threadIdx.x;
    const int lane = tid & 31;
    const int wid  = tid >> 5;
    const int wm   = wid & 1;
    const int wn   = wid >> 1;
    const int g    = lane >> 2;
    const int t    = lane & 3;

    const __half* Abase = g_X + (size_t)blockIdx.x * GBM * KDIM;
    const __half* Bbase = g_M + (size_t)blockIdx.y * GBN * KDIM;

    float acc[4][8][4];
#pragma unroll
    for (int i = 0; i < 4; ++i)
#pragma unroll
        for (int j = 0; j < 8; ++j)
#pragma unroll
            for (int r = 0; r < 4; ++r) acc[i][j][r] = 0.f;

    // fill one stage: A 128 rows x 128B + B same = 2048 16B chunks, 16/thread
#define FILL_STAGE(slot, kc)                                                   \
    {                                                                          \
        __half* sA_ = smemh + (slot) * STAGE_TOT;                              \
        __half* sB_ = sA_ + STAGE_H;                                           \
        const int ko_ = (kc) * BKH;                                            \
        _Pragma("unroll")                                                      \
        for (int i_ = 0; i_ < 8; ++i_) {                                       \
            int ch_ = tid + i_ * 128;                                          \
            int r_  = ch_ >> 3;                                                \
            int c_  = ch_ & 7;                                                 \
            cp_async16(sA_ + r_ * SROWH + c_ * 8,                              \
                       Abase + (size_t)r_ * KDIM + ko_ + c_ * 8);              \
            cp_async16(sB_ + r_ * SROWH + c_ * 8,                              \
                       Bbase + (size_t)r_ * KDIM + ko_ + c_ * 8);              \
        }                                                                      \
        asm volatile("cp.async.commit_group;");                                \
    }

    FILL_STAGE(0, 0)

    for (int kc = 0; kc < NKC; ++kc) {
        if (kc + 1 < NKC) {
            FILL_STAGE((kc + 1) & 1, kc + 1)
            asm volatile("cp.async.wait_group 1;" ::: "memory");
        } else {
            asm volatile("cp.async.wait_group 0;" ::: "memory");
        }
        __syncthreads();

        const __half* As = smemh + (kc & 1) * STAGE_TOT;
        const __half* Bs = As + STAGE_H;

#pragma unroll
        for (int kk = 0; kk < 4; ++kk) {          // four K16 groups per panel
            const int coff = kk * 16 + t * 4;     // halves
            uint2 alo[4], ahi[4];
#pragma unroll
            for (int mi = 0; mi < 4; ++mi) {
                int r0 = wm * 64 + mi * 16 + g;
                alo[mi] = *reinterpret_cast<const uint2*>(As + r0 * SROWH + coff);
                ahi[mi] = *reinterpret_cast<const uint2*>(As + (r0 + 8) * SROWH + coff);
            }
#pragma unroll
            for (int nj = 0; nj < 8; ++nj) {
                int cn = wn * 64 + nj * 8 + g;
                uint2 b = *reinterpret_cast<const uint2*>(Bs + cn * SROWH + coff);
#pragma unroll
                for (int mi = 0; mi < 4; ++mi) {
                    asm volatile(
                        "mma.sync.aligned.m16n8k16.row.col.f32.f16.f16.f32 "
                        "{%0,%1,%2,%3}, {%4,%5,%6,%7}, {%8,%9}, {%0,%1,%2,%3};"
                        : "+f"(acc[mi][nj][0]), "+f"(acc[mi][nj][1]),
                          "+f"(acc[mi][nj][2]), "+f"(acc[mi][nj][3])
                        : "r"(alo[mi].x), "r"(ahi[mi].x),
                          "r"(alo[mi].y), "r"(ahi[mi].y),
                          "r"(b.x), "r"(b.y));
                }
            }
        }
        __syncthreads();
    }
#undef FILL_STAGE

    // ---- epilogue: relu -> Cs[128][132] -> bag-mean(8) -> out ----
    float* Cs = reinterpret_cast<float*>(dynsm);
#pragma unroll
    for (int mi = 0; mi < 4; ++mi) {
#pragma unroll
        for (int nj = 0; nj < 8; ++nj) {
            int r0 = wm * 64 + mi * 16 + g;
            int c0 = wn * 64 + nj * 8 + 2 * t;
            Cs[r0 * CLD + c0]           = fmaxf(acc[mi][nj][0], 0.f);
            Cs[r0 * CLD + c0 + 1]       = fmaxf(acc[mi][nj][1], 0.f);
            Cs[(r0 + 8) * CLD + c0]     = fmaxf(acc[mi][nj][2], 0.f);
            Cs[(r0 + 8) * CLD + c0 + 1] = fmaxf(acc[mi][nj][3], 0.f);
        }
    }
    __syncthreads();

    const int col = tid;
#pragma unroll
    for (int gg = 0; gg < GBM / BAG; ++gg) {
        float s = 0.f;
#pragma unroll
        for (int r = 0; r < BAG; ++r) s += Cs[(gg * BAG + r) * CLD + col];
        out[(size_t)(blockIdx.x * (GBM / BAG) + gg) * OUTD + blockIdx.y * GBN + col]
            = s * (1.f / BAG);
    }
}

// ---------------------------------------------------------------------------
namespace {
struct HxSide {
    cudaStream_t side;
    cudaEvent_t  evFork, evJoin;
    HxSide() {
        cudaStreamCreateWithFlags(&side, cudaStreamNonBlocking);
        cudaEventCreateWithFlags(&evFork, cudaEventDisableTiming);
        cudaEventCreateWithFlags(&evJoin, cudaEventDisableTiming);
    }
};
HxSide hx;
}

extern "C" void kernel_launch(void* const* d_in, const int* in_sizes, int n_in,
                              void* d_out, int out_size)
{
    (void)in_sizes; (void)n_in; (void)out_size;
    const int*   nodes      = (const int*)  d_in[0];
    const int*   neigh_idx  = (const int*)  d_in[1];
    const float* table_self = (const float*)d_in[2];
    const float* tables_to  = (const float*)d_in[3];
    const float* W_self     = (const float*)d_in[4];
    const float* W_rel      = (const float*)d_in[5];
    const float* W_comp     = (const float*)d_in[6];
    float*       out        = (float*)d_out;

    cudaFuncSetAttribute(gemm_relu_bag_kernel,
                         cudaFuncAttributeMaxDynamicSharedMemorySize,
                         G_SMEM_BYTES);

    cudaEventRecord(hx.evFork, 0);
    gather_mean_kernel<<<dim3(NN / 4, 4), 256>>>(nodes, neigh_idx, table_self, tables_to);

    cudaStreamWaitEvent(hx.side, hx.evFork, 0);
    fuse_weights_kernel<<<512, 256, 0, hx.side>>>(W_self, W_rel, W_comp);
    cudaEventRecord(hx.evJoin, hx.side);

    cudaStreamWaitEvent(0, hx.evJoin, 0);
    gemm_relu_bag_kernel<<<dim3(NN / GBM, OUTD / GBN), 128, G_SMEM_BYTES>>>(out);
}